// round 16
// baseline (speedup 1.0000x reference)
#include <cuda_runtime.h>
#include <cuda_fp16.h>
#include <math.h>
#include <stdint.h>

#define BATCH 2
#define SEQ   2048
#define NEMBD 1024
#define NHEAD 16
#define HSZ   64
#define FFDIM 4096
#define BT    (BATCH*SEQ)      // 4096 rows
#define QKV_LD 3072
#define LN_EPS 1e-5f
#define ATT_SCALE 0.03125f     // 1024^-0.5

// ---------------- scratch (device globals; no allocation allowed) ----------------
__device__ __half g_h[(size_t)BT*NEMBD];
__device__ __half g_qkv[(size_t)BT*QKV_LD];
__device__ __half g_attn[(size_t)BT*NEMBD];
__device__ float  g_x2[(size_t)BT*NEMBD];
__device__ __half g_f1[(size_t)BT*FFDIM];
__device__ __half g_wr[(size_t)12*1024*1024];  // Wqkv_t[3072][1024] Wpt[1024][1024] W1t[4096][1024] W2t[1024][4096]

// ---------------- helpers ----------------
__device__ __forceinline__ void mma_f16(float* c, const uint32_t* a, const uint32_t* b) {
    asm volatile(
        "mma.sync.aligned.m16n8k16.row.col.f32.f16.f16.f32 "
        "{%0,%1,%2,%3}, {%4,%5,%6,%7}, {%8,%9}, {%0,%1,%2,%3};"
        : "+f"(c[0]), "+f"(c[1]), "+f"(c[2]), "+f"(c[3])
        : "r"(a[0]), "r"(a[1]), "r"(a[2]), "r"(a[3]), "r"(b[0]), "r"(b[1]));
}
__device__ __forceinline__ void cp_async16(uint32_t saddr, const void* gaddr) {
    asm volatile("cp.async.cg.shared.global [%0], [%1], 16;" :: "r"(saddr), "l"(gaddr));
}
__device__ __forceinline__ void cp_commit() {
    asm volatile("cp.async.commit_group;");
}
template<int N>
__device__ __forceinline__ void cp_wait() {
    asm volatile("cp.async.wait_group %0;" :: "n"(N));
}
__device__ __forceinline__ uint32_t smem_u32(const void* p) {
    return (uint32_t)__cvta_generic_to_shared(p);
}

// ---------------- weight transpose + half round: in fp32 [K][N] -> out half [N][K] ----------------
__global__ void transpose_round_h(const float* __restrict__ in, __half* __restrict__ out,
                                  int K, int N)
{
    __shared__ float t[32][33];
    int kb = blockIdx.y*32, nb = blockIdx.x*32;
    int tx = threadIdx.x, ty = threadIdx.y;   // (32, 8)
    #pragma unroll
    for (int i=0;i<32;i+=8)
        t[ty+i][tx] = in[(long long)(kb+ty+i)*N + nb+tx];
    __syncthreads();
    #pragma unroll
    for (int i=0;i<32;i+=8)
        out[(long long)(nb+ty+i)*K + kb+tx] = __float2half_rn(t[tx][ty+i]);
}

// ---------------- LayerNorm: one block per row; fp32 in, half out ----------------
__global__ void ln_kernel(const float* __restrict__ x, const float* __restrict__ w,
                          const float* __restrict__ b, __half* __restrict__ out)
{
    int row = blockIdx.x;
    const float4* xr = (const float4*)(x + (size_t)row*NEMBD);
    int t = threadIdx.x;
    float4 v = xr[t];
    float s  = v.x + v.y + v.z + v.w;
    float s2 = v.x*v.x + v.y*v.y + v.z*v.z + v.w*v.w;
    #pragma unroll
    for (int o = 16; o > 0; o >>= 1) {
        s  += __shfl_xor_sync(0xffffffffu, s,  o);
        s2 += __shfl_xor_sync(0xffffffffu, s2, o);
    }
    __shared__ float ss[8], ss2[8];
    int wid = t >> 5, lid = t & 31;
    if (lid == 0) { ss[wid] = s; ss2[wid] = s2; }
    __syncthreads();
    if (wid == 0) {
        float a  = (lid < 8) ? ss[lid]  : 0.f;
        float a2 = (lid < 8) ? ss2[lid] : 0.f;
        #pragma unroll
        for (int o = 4; o > 0; o >>= 1) {
            a  += __shfl_xor_sync(0xffffffffu, a,  o);
            a2 += __shfl_xor_sync(0xffffffffu, a2, o);
        }
        if (lid == 0) { ss[0] = a; ss2[0] = a2; }
    }
    __syncthreads();
    float mu  = ss[0]  * (1.0f/NEMBD);
    float var = ss2[0] * (1.0f/NEMBD) - mu*mu;
    float inv = rsqrtf(var + LN_EPS);
    const float4 wv = ((const float4*)w)[t];
    const float4 bv = ((const float4*)b)[t];
    __half2 h0 = __floats2half2_rn((v.x - mu)*inv*wv.x + bv.x, (v.y - mu)*inv*wv.y + bv.y);
    __half2 h1 = __floats2half2_rn((v.z - mu)*inv*wv.z + bv.z, (v.w - mu)*inv*wv.w + bv.w);
    __half2* orow = (__half2*)(out + (size_t)row*NEMBD);
    orow[2*t]   = h0;
    orow[2*t+1] = h1;
}

// ---------------- fp16 tensor-core GEMM, cp.async pipeline ----------------
// BM=128 fixed; BN/NT templated: (128,4) = proven 64x32 warp tiles @occ2,
// (256,8) = 64x64 warp tiles @occ1 (less fragment traffic per MAC).
#define ROWB 80
template<int STAGES,int OUT_HALF,int BN,int NT,int OCC>
__global__ void __launch_bounds__(256, OCC)
hgemm(const __half* __restrict__ A, const __half* __restrict__ Bt,
      const float* __restrict__ bias, const float* __restrict__ res,
      void* __restrict__ Cv,
      int M, int N, int K, int ldc, int relu)
{
    constexpr int MT = 4;
    constexpr int WN = NT*8;
    constexpr int A_STAGE = 128*ROWB;
    constexpr int B_STAGE = BN*ROWB;
    constexpr int B_ITERS = (BN*4)/256;

    extern __shared__ char smem[];
    uint32_t sA = smem_u32(smem);
    uint32_t sB = sA + STAGES*A_STAGE;

    int tid = threadIdx.x;
    int wid = tid >> 5;
    int lane = tid & 31;
    int grp = lane >> 2;
    int qid = lane & 3;
    int warpRow = wid >> 2;      // 0..1 -> 64 rows
    int warpCol = wid & 3;       // 0..3 -> WN cols

    int row0 = blockIdx.y * 128;
    int col0 = blockIdx.x * BN;

    float acc[MT][NT][4];
    #pragma unroll
    for (int i=0;i<MT;i++)
        #pragma unroll
        for (int j=0;j<NT;j++) {
            acc[i][j][0]=0.f; acc[i][j][1]=0.f; acc[i][j][2]=0.f; acc[i][j][3]=0.f;
        }

    int nIter = K / 32;

    auto issue = [&](int s, int buf) {
        #pragma unroll
        for (int t=0; t<2; t++) {
            int ch = tid + t*256;
            int r = ch >> 2;
            int c = ch & 3;
            cp_async16(sA + buf*A_STAGE + r*ROWB + c*16,
                       A + (long long)(row0 + r)*K + s*32 + c*8);
        }
        #pragma unroll
        for (int t=0; t<B_ITERS; t++) {
            int ch = tid + t*256;
            int n = ch >> 2;
            int c = ch & 3;
            cp_async16(sB + buf*B_STAGE + n*ROWB + c*16,
                       Bt + (long long)(col0 + n)*K + s*32 + c*8);
        }
    };

    #pragma unroll
    for (int s=0; s<STAGES-1; s++) {
        if (s < nIter) issue(s, s);
        cp_commit();
    }

    const char* smc = (const char*)smem;
    for (int it = 0; it < nIter; it++) {
        cp_wait<STAGES-2>();
        __syncthreads();

        int cur = it % STAGES;
        int nx = it + STAGES - 1;
        if (nx < nIter) issue(nx, nx % STAGES);
        cp_commit();

        const char* Ac = smc + cur*A_STAGE;
        const char* Bc = smc + STAGES*A_STAGE + cur*B_STAGE;

        #pragma unroll
        for (int ks = 0; ks < 2; ks++) {
            int kb = ks*32;
            uint32_t af[MT][4];
            uint32_t bf[NT][2];
            #pragma unroll
            for (int mt=0; mt<MT; mt++) {
                int rr = warpRow*64 + mt*16 + grp;
                const char* base = Ac + rr*ROWB + kb + qid*4;
                af[mt][0] = *(const uint32_t*)(base);
                af[mt][1] = *(const uint32_t*)(base + 8*ROWB);
                af[mt][2] = *(const uint32_t*)(base + 16);
                af[mt][3] = *(const uint32_t*)(base + 8*ROWB + 16);
            }
            #pragma unroll
            for (int nt=0; nt<NT; nt++) {
                int nn = warpCol*WN + nt*8 + grp;
                const char* base = Bc + nn*ROWB + kb + qid*4;
                bf[nt][0] = *(const uint32_t*)(base);
                bf[nt][1] = *(const uint32_t*)(base + 16);
            }
            #pragma unroll
            for (int mt=0; mt<MT; mt++)
                #pragma unroll
                for (int nt=0; nt<NT; nt++)
                    mma_f16(acc[mt][nt], af[mt], bf[nt]);
        }
        __syncthreads();
    }

    #pragma unroll
    for (int mt=0; mt<MT; mt++) {
        int rA = row0 + warpRow*64 + mt*16 + grp;
        int rB = rA + 8;
        #pragma unroll
        for (int nt=0; nt<NT; nt++) {
            int c = col0 + warpCol*WN + nt*8 + qid*2;
            float v0 = acc[mt][nt][0];
            float v1 = acc[mt][nt][1];
            float v2 = acc[mt][nt][2];
            float v3 = acc[mt][nt][3];
            if (bias) {
                float2 bb2 = *(const float2*)(bias + c);
                v0 += bb2.x; v1 += bb2.y; v2 += bb2.x; v3 += bb2.y;
            }
            if (relu) {
                v0 = fmaxf(v0,0.f); v1 = fmaxf(v1,0.f);
                v2 = fmaxf(v2,0.f); v3 = fmaxf(v3,0.f);
            }
            if (res) {
                float2 rA2 = *(const float2*)(res + (long long)rA*ldc + c);
                float2 rB2 = *(const float2*)(res + (long long)rB*ldc + c);
                v0 += rA2.x; v1 += rA2.y; v2 += rB2.x; v3 += rB2.y;
            }
            if (OUT_HALF) {
                __half* C = (__half*)Cv;
                *(__half2*)(C + (long long)rA*ldc + c) = __floats2half2_rn(v0, v1);
                *(__half2*)(C + (long long)rB*ldc + c) = __floats2half2_rn(v2, v3);
            } else {
                float* C = (float*)Cv;
                *(float2*)(C + (long long)rA*ldc + c) = make_float2(v0, v1);
                *(float2*)(C + (long long)rB*ldc + c) = make_float2(v2, v3);
            }
        }
    }
}

// ---------------- fused flash attention, all-f16 mma, causal (R14 proven) ----------------
#define FH_S 72
#define FA_SMEM ((128*FH_S + 64*FH_S + 64*FH_S + 128*FH_S)*2)   // 55296 B

__global__ void __launch_bounds__(256, 2)
flash_kernel(const __half* __restrict__ qkv, __half* __restrict__ attn)
{
    extern __shared__ __half fh[];
    __half* Qs = fh;                      // [128][FH_S]
    __half* Ks = Qs + 128*FH_S;           // [64][FH_S]
    __half* Vt = Ks + 64*FH_S;            // [64][FH_S]  (d, s)
    __half* Ps = Vt + 64*FH_S;            // [128][FH_S]

    int q0 = blockIdx.x * 128;
    int bh = blockIdx.y;
    int b = bh >> 4, h = bh & 15;
    const __half* Qg = qkv + (long long)b*SEQ*QKV_LD + h*HSZ;
    const __half* Kg = Qg + NEMBD;
    const __half* Vg = Qg + 2*NEMBD;

    int tid = threadIdx.x;
    int wid = tid >> 5;
    int lane = tid & 31;
    int grp = lane >> 2;
    int qid = lane & 3;
    int w16 = wid * 16;

    #pragma unroll
    for (int t = 0; t < 4; t++) {
        int ch = tid + t*256;
        int r = ch >> 3, c8 = (ch & 7) << 3;
        *(uint4*)&Qs[r*FH_S + c8] = *(const uint4*)(Qg + (long long)(q0 + r)*QKV_LD + c8);
    }

    float m0 = -INFINITY, m1 = -INFINITY, l0 = 0.f, l1 = 0.f;
    float O[8][4];
    #pragma unroll
    for (int nt=0; nt<8; nt++) { O[nt][0]=0.f; O[nt][1]=0.f; O[nt][2]=0.f; O[nt][3]=0.f; }

    int t0 = q0 + w16 + grp;
    int t1 = t0 + 8;
    int nkv = q0/64 + 2;

    for (int kj = 0; kj < nkv; kj++) {
        int s0 = kj * 64;
        __syncthreads();

        #pragma unroll
        for (int t = 0; t < 2; t++) {
            int ch = tid + t*256;
            int r = ch >> 3, c8 = (ch & 7) << 3;
            *(uint4*)&Ks[r*FH_S + c8] = *(const uint4*)(Kg + (long long)(s0 + r)*QKV_LD + c8);
        }
        #pragma unroll
        for (int t = 0; t < 2; t++) {
            int ch = tid + t*256;
            int s = ch >> 3, d0 = (ch & 7) << 3;
            uint4 u = *(const uint4*)(Vg + (long long)(s0 + s)*QKV_LD + d0);
            const __half* hp = (const __half*)&u;
            #pragma unroll
            for (int j = 0; j < 8; j++)
                Vt[(d0 + j)*FH_S + s] = hp[j];
        }
        __syncthreads();

        float sacc[8][4];
        #pragma unroll
        for (int nt=0; nt<8; nt++) { sacc[nt][0]=0.f; sacc[nt][1]=0.f; sacc[nt][2]=0.f; sacc[nt][3]=0.f; }

        #pragma unroll
        for (int ks = 0; ks < 4; ks++) {
            int kb = ks*16;
            uint32_t a[4];
            const __half* Abase = &Qs[(w16 + grp)*FH_S + kb + 2*qid];
            a[0] = *(const uint32_t*)(Abase);
            a[1] = *(const uint32_t*)(Abase + 8*FH_S);
            a[2] = *(const uint32_t*)(Abase + 8);
            a[3] = *(const uint32_t*)(Abase + 8*FH_S + 8);
            #pragma unroll
            for (int nt=0; nt<8; nt++) {
                const __half* Bbase = &Ks[(nt*8 + grp)*FH_S + kb + 2*qid];
                uint32_t bb[2];
                bb[0] = *(const uint32_t*)(Bbase);
                bb[1] = *(const uint32_t*)(Bbase + 8);
                mma_f16(sacc[nt], a, bb);
            }
        }

        #pragma unroll
        for (int nt=0; nt<8; nt++) {
            int c = s0 + nt*8 + 2*qid;
            sacc[nt][0] = (c   <= t0) ? sacc[nt][0]*ATT_SCALE : -INFINITY;
            sacc[nt][1] = (c+1 <= t0) ? sacc[nt][1]*ATT_SCALE : -INFINITY;
            sacc[nt][2] = (c   <= t1) ? sacc[nt][2]*ATT_SCALE : -INFINITY;
            sacc[nt][3] = (c+1 <= t1) ? sacc[nt][3]*ATT_SCALE : -INFINITY;
        }

        float ml0 = -INFINITY, ml1 = -INFINITY;
        #pragma unroll
        for (int nt=0; nt<8; nt++) {
            ml0 = fmaxf(ml0, fmaxf(sacc[nt][0], sacc[nt][1]));
            ml1 = fmaxf(ml1, fmaxf(sacc[nt][2], sacc[nt][3]));
        }
        ml0 = fmaxf(ml0, __shfl_xor_sync(0xffffffffu, ml0, 1));
        ml0 = fmaxf(ml0, __shfl_xor_sync(0xffffffffu, ml0, 2));
        ml1 = fmaxf(ml1, __shfl_xor_sync(0xffffffffu, ml1, 1));
        ml1 = fmaxf(ml1, __shfl_xor_sync(0xffffffffu, ml1, 2));

        float mn0 = fmaxf(m0, ml0);
        float mn1 = fmaxf(m1, ml1);
        float al0 = __expf(m0 - mn0);
        float al1 = __expf(m1 - mn1);

        float sum0 = 0.f, sum1 = 0.f;
        #pragma unroll
        for (int nt=0; nt<8; nt++) {
            float p00 = __expf(sacc[nt][0] - mn0);
            float p01 = __expf(sacc[nt][1] - mn0);
            float p10 = __expf(sacc[nt][2] - mn1);
            float p11 = __expf(sacc[nt][3] - mn1);
            sum0 += p00 + p01;
            sum1 += p10 + p11;
            int c = nt*8 + 2*qid;
            *(__half2*)&Ps[(w16+grp  )*FH_S + c] = __floats2half2_rn(p00, p01);
            *(__half2*)&Ps[(w16+grp+8)*FH_S + c] = __floats2half2_rn(p10, p11);
        }
        sum0 += __shfl_xor_sync(0xffffffffu, sum0, 1);
        sum0 += __shfl_xor_sync(0xffffffffu, sum0, 2);
        sum1 += __shfl_xor_sync(0xffffffffu, sum1, 1);
        sum1 += __shfl_xor_sync(0xffffffffu, sum1, 2);

        l0 = l0*al0 + sum0;
        l1 = l1*al1 + sum1;
        #pragma unroll
        for (int nt=0; nt<8; nt++) {
            O[nt][0] *= al0; O[nt][1] *= al0;
            O[nt][2] *= al1; O[nt][3] *= al1;
        }
        m0 = mn0; m1 = mn1;
        __syncwarp();

        #pragma unroll
        for (int ks = 0; ks < 4; ks++) {
            int kb = ks*16;
            uint32_t a[4];
            const __half* Abase = &Ps[(w16 + grp)*FH_S + kb + 2*qid];
            a[0] = *(const uint32_t*)(Abase);
            a[1] = *(const uint32_t*)(Abase + 8*FH_S);
            a[2] = *(const uint32_t*)(Abase + 8);
            a[3] = *(const uint32_t*)(Abase + 8*FH_S + 8);
            #pragma unroll
            for (int nt=0; nt<8; nt++) {
                const __half* Bbase = &Vt[(nt*8 + grp)*FH_S + kb + 2*qid];
                uint32_t bb[2];
                bb[0] = *(const uint32_t*)(Bbase);
                bb[1] = *(const uint32_t*)(Bbase + 8);
                mma_f16(O[nt], a, bb);
            }
        }
    }

    float inv0 = 1.0f / l0;
    float inv1 = 1.0f / l1;
    __half* outA = attn + ((long long)(b*SEQ + t0))*NEMBD + h*HSZ;
    __half* outB = attn + ((long long)(b*SEQ + t1))*NEMBD + h*HSZ;
    #pragma unroll
    for (int nt=0; nt<8; nt++) {
        int c = nt*8 + 2*qid;
        *(__half2*)(outA + c) = __floats2half2_rn(O[nt][0]*inv0, O[nt][1]*inv0);
        *(__half2*)(outB + c) = __floats2half2_rn(O[nt][2]*inv1, O[nt][3]*inv1);
    }
}

// ---------------- launch ----------------
extern "C" void kernel_launch(void* const* d_in, const int* in_sizes, int n_in,
                              void* d_out, int out_size)
{
    const float* x     = (const float*)d_in[0];
    const float* Wq    = (const float*)d_in[1];
    const float* Wk    = (const float*)d_in[2];
    const float* Wv    = (const float*)d_in[3];
    const float* Wproj = (const float*)d_in[4];
    const float* bproj = (const float*)d_in[5];
    const float* W1    = (const float*)d_in[6];
    const float* b1    = (const float*)d_in[7];
    const float* W2    = (const float*)d_in[8];
    const float* b2    = (const float*)d_in[9];
    const float* ln1w  = (const float*)d_in[10];
    const float* ln1b  = (const float*)d_in[11];
    const float* ln2w  = (const float*)d_in[12];
    const float* ln2b  = (const float*)d_in[13];
    float* out = (float*)d_out;

    __half *ph, *pqkv, *pattn, *pf1, *pwr;
    float *px2;
    cudaGetSymbolAddress((void**)&ph,    g_h);
    cudaGetSymbolAddress((void**)&pqkv,  g_qkv);
    cudaGetSymbolAddress((void**)&pattn, g_attn);
    cudaGetSymbolAddress((void**)&px2,   g_x2);
    cudaGetSymbolAddress((void**)&pf1,   g_f1);
    cudaGetSymbolAddress((void**)&pwr,   g_wr);

    const size_t M1 = (size_t)1024*1024;
    __half* Wqkvt = pwr;            // [3072][1024]
    __half* Wpt   = pwr + 3*M1;     // [1024][1024]
    __half* W1t   = pwr + 4*M1;     // [4096][1024]
    __half* W2t   = pwr + 8*M1;     // [1024][4096]

    constexpr int ST = 4;
    constexpr size_t SMEM_G128 = (size_t)ST*(128+128)*ROWB;   // 81920 B
    constexpr size_t SMEM_G256 = (size_t)ST*(128+256)*ROWB;   // 122880 B

    auto* kh128 = hgemm<ST,1,128,4,2>;   // proven narrow, occ 2
    auto* kf128 = hgemm<ST,0,128,4,2>;
    auto* kh256 = hgemm<ST,1,256,8,1>;   // wide 64x64 warp tiles, occ 1
    cudaFuncSetAttribute(kh128, cudaFuncAttributeMaxDynamicSharedMemorySize, (int)SMEM_G128);
    cudaFuncSetAttribute(kf128, cudaFuncAttributeMaxDynamicSharedMemorySize, (int)SMEM_G128);
    cudaFuncSetAttribute(kh256, cudaFuncAttributeMaxDynamicSharedMemorySize, (int)SMEM_G256);
    cudaFuncSetAttribute(flash_kernel, cudaFuncAttributeMaxDynamicSharedMemorySize, (int)FA_SMEM);

    // 0) transpose + half-round all weights (once per replay)
    {
        dim3 blk(32, 8);
        transpose_round_h<<<dim3(32, 32),  blk>>>(Wq,    Wqkvt,        1024, 1024);
        transpose_round_h<<<dim3(32, 32),  blk>>>(Wk,    Wqkvt + M1,   1024, 1024);
        transpose_round_h<<<dim3(32, 32),  blk>>>(Wv,    Wqkvt + 2*M1, 1024, 1024);
        transpose_round_h<<<dim3(32, 32),  blk>>>(Wproj, Wpt,          1024, 1024);
        transpose_round_h<<<dim3(128, 32), blk>>>(W1,    W1t,          1024, 4096);
        transpose_round_h<<<dim3(32, 128), blk>>>(W2,    W2t,          4096, 1024);
    }

    // 1) LN1 -> half
    ln_kernel<<<BT, 256>>>(x, ln1w, ln1b, ph);

    // 2) fused QKV (wide tiles): h[BT,1024] @ Wqkv -> g_qkv (half out)
    kh256<<<dim3(QKV_LD/256, BT/128), 256, SMEM_G256>>>(ph, Wqkvt, nullptr, nullptr, pqkv,
        BT, QKV_LD, NEMBD, QKV_LD, 0);

    // 3) fused flash attention -> g_attn (half out)
    flash_kernel<<<dim3(SEQ/128, BATCH*NHEAD), 256, FA_SMEM>>>(pqkv, pattn);

    // 4) x2 = x + attn @ Wproj + bproj  (float out, narrow)
    kf128<<<dim3(NEMBD/128, BT/128), 256, SMEM_G128>>>(pattn, Wpt, bproj, x, px2,
        BT, NEMBD, NEMBD, NEMBD, 0);

    // 5) LN2 -> half
    ln_kernel<<<BT, 256>>>(px2, ln2w, ln2b, ph);

    // 6) f1 = relu(h2 @ W1 + b1) (wide tiles, half out)
    kh256<<<dim3(FFDIM/256, BT/128), 256, SMEM_G256>>>(ph, W1t, b1, nullptr, pf1,
        BT, FFDIM, NEMBD, FFDIM, 1);

    // 7) out = x2 + f1 @ W2 + b2 (float out, narrow)
    kf128<<<dim3(NEMBD/128, BT/128), 256, SMEM_G128>>>(pf1, W2t, b2, px2, out,
        BT, NEMBD, FFDIM, NEMBD, 0);
}

// round 17
// speedup vs baseline: 1.0125x; 1.0125x over previous
#include <cuda_runtime.h>
#include <cuda_fp16.h>
#include <math.h>
#include <stdint.h>

#define BATCH 2
#define SEQ   2048
#define NEMBD 1024
#define NHEAD 16
#define HSZ   64
#define FFDIM 4096
#define BT    (BATCH*SEQ)      // 4096 rows
#define QKV_LD 3072
#define LN_EPS 1e-5f
#define ATT_SCALE 0.03125f     // 1024^-0.5

// ---------------- scratch (device globals; no allocation allowed) ----------------
__device__ __half g_h[(size_t)BT*NEMBD];
__device__ __half g_qkv[(size_t)BT*QKV_LD];
__device__ __half g_attn[(size_t)BT*NEMBD];
__device__ float  g_x2[(size_t)BT*NEMBD];
__device__ __half g_f1[(size_t)BT*FFDIM];
__device__ __half g_wr[(size_t)12*1024*1024];  // Wqkv_t[3072][1024] Wpt[1024][1024] W1t[4096][1024] W2t[1024][4096]

// ---------------- helpers ----------------
__device__ __forceinline__ void mma_f16(float* c, const uint32_t* a, const uint32_t* b) {
    asm volatile(
        "mma.sync.aligned.m16n8k16.row.col.f32.f16.f16.f32 "
        "{%0,%1,%2,%3}, {%4,%5,%6,%7}, {%8,%9}, {%0,%1,%2,%3};"
        : "+f"(c[0]), "+f"(c[1]), "+f"(c[2]), "+f"(c[3])
        : "r"(a[0]), "r"(a[1]), "r"(a[2]), "r"(a[3]), "r"(b[0]), "r"(b[1]));
}
__device__ __forceinline__ void cp_async16(uint32_t saddr, const void* gaddr) {
    asm volatile("cp.async.cg.shared.global [%0], [%1], 16;" :: "r"(saddr), "l"(gaddr));
}
__device__ __forceinline__ void cp_commit() {
    asm volatile("cp.async.commit_group;");
}
template<int N>
__device__ __forceinline__ void cp_wait() {
    asm volatile("cp.async.wait_group %0;" :: "n"(N));
}
__device__ __forceinline__ uint32_t smem_u32(const void* p) {
    return (uint32_t)__cvta_generic_to_shared(p);
}

// ---------------- batched weight transpose + half round (square 1024x1024 x4) ----------------
struct TP4 { const float* src[4]; __half* dst[4]; };

__global__ void transpose_round_h4(TP4 args)
{
    __shared__ float t[32][33];
    const float* in = args.src[blockIdx.z];
    __half* out = args.dst[blockIdx.z];
    const int K = 1024, N = 1024;
    int kb = blockIdx.y*32, nb = blockIdx.x*32;
    int tx = threadIdx.x, ty = threadIdx.y;   // (32, 8)
    #pragma unroll
    for (int i=0;i<32;i+=8)
        t[ty+i][tx] = in[(long long)(kb+ty+i)*N + nb+tx];
    __syncthreads();
    #pragma unroll
    for (int i=0;i<32;i+=8)
        out[(long long)(nb+ty+i)*K + kb+tx] = __float2half_rn(t[tx][ty+i]);
}

// ---------------- weight transpose + half round (general) ----------------
__global__ void transpose_round_h(const float* __restrict__ in, __half* __restrict__ out,
                                  int K, int N)
{
    __shared__ float t[32][33];
    int kb = blockIdx.y*32, nb = blockIdx.x*32;
    int tx = threadIdx.x, ty = threadIdx.y;   // (32, 8)
    #pragma unroll
    for (int i=0;i<32;i+=8)
        t[ty+i][tx] = in[(long long)(kb+ty+i)*N + nb+tx];
    __syncthreads();
    #pragma unroll
    for (int i=0;i<32;i+=8)
        out[(long long)(nb+ty+i)*K + kb+tx] = __float2half_rn(t[tx][ty+i]);
}

// ---------------- LayerNorm: one block per row; fp32 in, half out ----------------
__global__ void ln_kernel(const float* __restrict__ x, const float* __restrict__ w,
                          const float* __restrict__ b, __half* __restrict__ out)
{
    int row = blockIdx.x;
    const float4* xr = (const float4*)(x + (size_t)row*NEMBD);
    int t = threadIdx.x;
    float4 v = xr[t];
    float s  = v.x + v.y + v.z + v.w;
    float s2 = v.x*v.x + v.y*v.y + v.z*v.z + v.w*v.w;
    #pragma unroll
    for (int o = 16; o > 0; o >>= 1) {
        s  += __shfl_xor_sync(0xffffffffu, s,  o);
        s2 += __shfl_xor_sync(0xffffffffu, s2, o);
    }
    __shared__ float ss[8], ss2[8];
    int wid = t >> 5, lid = t & 31;
    if (lid == 0) { ss[wid] = s; ss2[wid] = s2; }
    __syncthreads();
    if (wid == 0) {
        float a  = (lid < 8) ? ss[lid]  : 0.f;
        float a2 = (lid < 8) ? ss2[lid] : 0.f;
        #pragma unroll
        for (int o = 4; o > 0; o >>= 1) {
            a  += __shfl_xor_sync(0xffffffffu, a,  o);
            a2 += __shfl_xor_sync(0xffffffffu, a2, o);
        }
        if (lid == 0) { ss[0] = a; ss2[0] = a2; }
    }
    __syncthreads();
    float mu  = ss[0]  * (1.0f/NEMBD);
    float var = ss2[0] * (1.0f/NEMBD) - mu*mu;
    float inv = rsqrtf(var + LN_EPS);
    const float4 wv = ((const float4*)w)[t];
    const float4 bv = ((const float4*)b)[t];
    __half2 h0 = __floats2half2_rn((v.x - mu)*inv*wv.x + bv.x, (v.y - mu)*inv*wv.y + bv.y);
    __half2 h1 = __floats2half2_rn((v.z - mu)*inv*wv.z + bv.z, (v.w - mu)*inv*wv.w + bv.w);
    __half2* orow = (__half2*)(out + (size_t)row*NEMBD);
    orow[2*t]   = h0;
    orow[2*t+1] = h1;
}

// ---------------- fp16 tensor-core GEMM, cp.async pipeline (R13/R14 proven config) ----------------
#define ROWB 80
#define HG_STAGE (128*ROWB)
template<int STAGES,int OUT_HALF>
__global__ void __launch_bounds__(256, 2)
hgemm(const __half* __restrict__ A, const __half* __restrict__ Bt,
      const float* __restrict__ bias, const float* __restrict__ res,
      void* __restrict__ Cv,
      int M, int N, int K, int ldc, int relu)
{
    constexpr int MT = 4, NT = 4;
    extern __shared__ char smem[];
    uint32_t sA = smem_u32(smem);
    uint32_t sB = sA + STAGES*HG_STAGE;

    int tid = threadIdx.x;
    int wid = tid >> 5;
    int lane = tid & 31;
    int grp = lane >> 2;
    int qid = lane & 3;
    int warpRow = wid >> 2;
    int warpCol = wid & 3;

    int row0 = blockIdx.y * 128;
    int col0 = blockIdx.x * 128;

    float acc[MT][NT][4];
    #pragma unroll
    for (int i=0;i<MT;i++)
        #pragma unroll
        for (int j=0;j<NT;j++) {
            acc[i][j][0]=0.f; acc[i][j][1]=0.f; acc[i][j][2]=0.f; acc[i][j][3]=0.f;
        }

    int nIter = K / 32;

    auto issue = [&](int s, int buf) {
        #pragma unroll
        for (int t=0; t<2; t++) {
            int ch = tid + t*256;
            int r = ch >> 2;
            int c = ch & 3;
            cp_async16(sA + buf*HG_STAGE + r*ROWB + c*16,
                       A + (long long)(row0 + r)*K + s*32 + c*8);
        }
        #pragma unroll
        for (int t=0; t<2; t++) {
            int ch = tid + t*256;
            int n = ch >> 2;
            int c = ch & 3;
            cp_async16(sB + buf*HG_STAGE + n*ROWB + c*16,
                       Bt + (long long)(col0 + n)*K + s*32 + c*8);
        }
    };

    #pragma unroll
    for (int s=0; s<STAGES-1; s++) {
        if (s < nIter) issue(s, s);
        cp_commit();
    }

    const char* smc = (const char*)smem;
    for (int it = 0; it < nIter; it++) {
        cp_wait<STAGES-2>();
        __syncthreads();

        int cur = it % STAGES;
        int nx = it + STAGES - 1;
        if (nx < nIter) issue(nx, nx % STAGES);
        cp_commit();

        const char* Ac = smc + cur*HG_STAGE;
        const char* Bc = smc + STAGES*HG_STAGE + cur*HG_STAGE;

        #pragma unroll
        for (int ks = 0; ks < 2; ks++) {
            int kb = ks*32;
            uint32_t af[MT][4];
            uint32_t bf[NT][2];
            #pragma unroll
            for (int mt=0; mt<MT; mt++) {
                int rr = warpRow*64 + mt*16 + grp;
                const char* base = Ac + rr*ROWB + kb + qid*4;
                af[mt][0] = *(const uint32_t*)(base);
                af[mt][1] = *(const uint32_t*)(base + 8*ROWB);
                af[mt][2] = *(const uint32_t*)(base + 16);
                af[mt][3] = *(const uint32_t*)(base + 8*ROWB + 16);
            }
            #pragma unroll
            for (int nt=0; nt<NT; nt++) {
                int nn = warpCol*32 + nt*8 + grp;
                const char* base = Bc + nn*ROWB + kb + qid*4;
                bf[nt][0] = *(const uint32_t*)(base);
                bf[nt][1] = *(const uint32_t*)(base + 16);
            }
            #pragma unroll
            for (int mt=0; mt<MT; mt++)
                #pragma unroll
                for (int nt=0; nt<NT; nt++)
                    mma_f16(acc[mt][nt], af[mt], bf[nt]);
        }
        __syncthreads();
    }

    #pragma unroll
    for (int mt=0; mt<MT; mt++) {
        int rA = row0 + warpRow*64 + mt*16 + grp;
        int rB = rA + 8;
        #pragma unroll
        for (int nt=0; nt<NT; nt++) {
            int c = col0 + warpCol*32 + nt*8 + qid*2;
            float v0 = acc[mt][nt][0];
            float v1 = acc[mt][nt][1];
            float v2 = acc[mt][nt][2];
            float v3 = acc[mt][nt][3];
            if (bias) {
                float2 bb2 = *(const float2*)(bias + c);
                v0 += bb2.x; v1 += bb2.y; v2 += bb2.x; v3 += bb2.y;
            }
            if (relu) {
                v0 = fmaxf(v0,0.f); v1 = fmaxf(v1,0.f);
                v2 = fmaxf(v2,0.f); v3 = fmaxf(v3,0.f);
            }
            if (res) {
                float2 rA2 = *(const float2*)(res + (long long)rA*ldc + c);
                float2 rB2 = *(const float2*)(res + (long long)rB*ldc + c);
                v0 += rA2.x; v1 += rA2.y; v2 += rB2.x; v3 += rB2.y;
            }
            if (OUT_HALF) {
                __half* C = (__half*)Cv;
                *(__half2*)(C + (long long)rA*ldc + c) = __floats2half2_rn(v0, v1);
                *(__half2*)(C + (long long)rB*ldc + c) = __floats2half2_rn(v2, v3);
            } else {
                float* C = (float*)Cv;
                *(float2*)(C + (long long)rA*ldc + c) = make_float2(v0, v1);
                *(float2*)(C + (long long)rB*ldc + c) = make_float2(v2, v3);
            }
        }
    }
}

// ---------------- fused flash attention, all-f16 mma, causal (R14 proven) ----------------
// Heavy blocks (large q0) launch first: q0 derived from reversed blockIdx.x.
#define FH_S 72
#define FA_SMEM ((128*FH_S + 64*FH_S + 64*FH_S + 128*FH_S)*2)   // 55296 B

__global__ void __launch_bounds__(256, 2)
flash_kernel(const __half* __restrict__ qkv, __half* __restrict__ attn)
{
    extern __shared__ __half fh[];
    __half* Qs = fh;                      // [128][FH_S]
    __half* Ks = Qs + 128*FH_S;           // [64][FH_S]
    __half* Vt = Ks + 64*FH_S;            // [64][FH_S]  (d, s)
    __half* Ps = Vt + 64*FH_S;            // [128][FH_S]

    int q0 = (gridDim.x - 1 - blockIdx.x) * 128;   // heavy tiles first
    int bh = blockIdx.y;
    int b = bh >> 4, h = bh & 15;
    const __half* Qg = qkv + (long long)b*SEQ*QKV_LD + h*HSZ;
    const __half* Kg = Qg + NEMBD;
    const __half* Vg = Qg + 2*NEMBD;

    int tid = threadIdx.x;
    int wid = tid >> 5;
    int lane = tid & 31;
    int grp = lane >> 2;
    int qid = lane & 3;
    int w16 = wid * 16;

    #pragma unroll
    for (int t = 0; t < 4; t++) {
        int ch = tid + t*256;
        int r = ch >> 3, c8 = (ch & 7) << 3;
        *(uint4*)&Qs[r*FH_S + c8] = *(const uint4*)(Qg + (long long)(q0 + r)*QKV_LD + c8);
    }

    float m0 = -INFINITY, m1 = -INFINITY, l0 = 0.f, l1 = 0.f;
    float O[8][4];
    #pragma unroll
    for (int nt=0; nt<8; nt++) { O[nt][0]=0.f; O[nt][1]=0.f; O[nt][2]=0.f; O[nt][3]=0.f; }

    int t0 = q0 + w16 + grp;
    int t1 = t0 + 8;
    int nkv = q0/64 + 2;

    for (int kj = 0; kj < nkv; kj++) {
        int s0 = kj * 64;
        __syncthreads();

        #pragma unroll
        for (int t = 0; t < 2; t++) {
            int ch = tid + t*256;
            int r = ch >> 3, c8 = (ch & 7) << 3;
            *(uint4*)&Ks[r*FH_S + c8] = *(const uint4*)(Kg + (long long)(s0 + r)*QKV_LD + c8);
        }
        #pragma unroll
        for (int t = 0; t < 2; t++) {
            int ch = tid + t*256;
            int s = ch >> 3, d0 = (ch & 7) << 3;
            uint4 u = *(const uint4*)(Vg + (long long)(s0 + s)*QKV_LD + d0);
            const __half* hp = (const __half*)&u;
            #pragma unroll
            for (int j = 0; j < 8; j++)
                Vt[(d0 + j)*FH_S + s] = hp[j];
        }
        __syncthreads();

        float sacc[8][4];
        #pragma unroll
        for (int nt=0; nt<8; nt++) { sacc[nt][0]=0.f; sacc[nt][1]=0.f; sacc[nt][2]=0.f; sacc[nt][3]=0.f; }

        #pragma unroll
        for (int ks = 0; ks < 4; ks++) {
            int kb = ks*16;
            uint32_t a[4];
            const __half* Abase = &Qs[(w16 + grp)*FH_S + kb + 2*qid];
            a[0] = *(const uint32_t*)(Abase);
            a[1] = *(const uint32_t*)(Abase + 8*FH_S);
            a[2] = *(const uint32_t*)(Abase + 8);
            a[3] = *(const uint32_t*)(Abase + 8*FH_S + 8);
            #pragma unroll
            for (int nt=0; nt<8; nt++) {
                const __half* Bbase = &Ks[(nt*8 + grp)*FH_S + kb + 2*qid];
                uint32_t bb[2];
                bb[0] = *(const uint32_t*)(Bbase);
                bb[1] = *(const uint32_t*)(Bbase + 8);
                mma_f16(sacc[nt], a, bb);
            }
        }

        #pragma unroll
        for (int nt=0; nt<8; nt++) {
            int c = s0 + nt*8 + 2*qid;
            sacc[nt][0] = (c   <= t0) ? sacc[nt][0]*ATT_SCALE : -INFINITY;
            sacc[nt][1] = (c+1 <= t0) ? sacc[nt][1]*ATT_SCALE : -INFINITY;
            sacc[nt][2] = (c   <= t1) ? sacc[nt][2]*ATT_SCALE : -INFINITY;
            sacc[nt][3] = (c+1 <= t1) ? sacc[nt][3]*ATT_SCALE : -INFINITY;
        }

        float ml0 = -INFINITY, ml1 = -INFINITY;
        #pragma unroll
        for (int nt=0; nt<8; nt++) {
            ml0 = fmaxf(ml0, fmaxf(sacc[nt][0], sacc[nt][1]));
            ml1 = fmaxf(ml1, fmaxf(sacc[nt][2], sacc[nt][3]));
        }
        ml0 = fmaxf(ml0, __shfl_xor_sync(0xffffffffu, ml0, 1));
        ml0 = fmaxf(ml0, __shfl_xor_sync(0xffffffffu, ml0, 2));
        ml1 = fmaxf(ml1, __shfl_xor_sync(0xffffffffu, ml1, 1));
        ml1 = fmaxf(ml1, __shfl_xor_sync(0xffffffffu, ml1, 2));

        float mn0 = fmaxf(m0, ml0);
        float mn1 = fmaxf(m1, ml1);
        float al0 = __expf(m0 - mn0);
        float al1 = __expf(m1 - mn1);

        float sum0 = 0.f, sum1 = 0.f;
        #pragma unroll
        for (int nt=0; nt<8; nt++) {
            float p00 = __expf(sacc[nt][0] - mn0);
            float p01 = __expf(sacc[nt][1] - mn0);
            float p10 = __expf(sacc[nt][2] - mn1);
            float p11 = __expf(sacc[nt][3] - mn1);
            sum0 += p00 + p01;
            sum1 += p10 + p11;
            int c = nt*8 + 2*qid;
            *(__half2*)&Ps[(w16+grp  )*FH_S + c] = __floats2half2_rn(p00, p01);
            *(__half2*)&Ps[(w16+grp+8)*FH_S + c] = __floats2half2_rn(p10, p11);
        }
        sum0 += __shfl_xor_sync(0xffffffffu, sum0, 1);
        sum0 += __shfl_xor_sync(0xffffffffu, sum0, 2);
        sum1 += __shfl_xor_sync(0xffffffffu, sum1, 1);
        sum1 += __shfl_xor_sync(0xffffffffu, sum1, 2);

        l0 = l0*al0 + sum0;
        l1 = l1*al1 + sum1;
        #pragma unroll
        for (int nt=0; nt<8; nt++) {
            O[nt][0] *= al0; O[nt][1] *= al0;
            O[nt][2] *= al1; O[nt][3] *= al1;
        }
        m0 = mn0; m1 = mn1;
        __syncwarp();

        #pragma unroll
        for (int ks = 0; ks < 4; ks++) {
            int kb = ks*16;
            uint32_t a[4];
            const __half* Abase = &Ps[(w16 + grp)*FH_S + kb + 2*qid];
            a[0] = *(const uint32_t*)(Abase);
            a[1] = *(const uint32_t*)(Abase + 8*FH_S);
            a[2] = *(const uint32_t*)(Abase + 8);
            a[3] = *(const uint32_t*)(Abase + 8*FH_S + 8);
            #pragma unroll
            for (int nt=0; nt<8; nt++) {
                const __half* Bbase = &Vt[(nt*8 + grp)*FH_S + kb + 2*qid];
                uint32_t bb[2];
                bb[0] = *(const uint32_t*)(Bbase);
                bb[1] = *(const uint32_t*)(Bbase + 8);
                mma_f16(O[nt], a, bb);
            }
        }
    }

    float inv0 = 1.0f / l0;
    float inv1 = 1.0f / l1;
    __half* outA = attn + ((long long)(b*SEQ + t0))*NEMBD + h*HSZ;
    __half* outB = attn + ((long long)(b*SEQ + t1))*NEMBD + h*HSZ;
    #pragma unroll
    for (int nt=0; nt<8; nt++) {
        int c = nt*8 + 2*qid;
        *(__half2*)(outA + c) = __floats2half2_rn(O[nt][0]*inv0, O[nt][1]*inv0);
        *(__half2*)(outB + c) = __floats2half2_rn(O[nt][2]*inv1, O[nt][3]*inv1);
    }
}

// ---------------- launch ----------------
extern "C" void kernel_launch(void* const* d_in, const int* in_sizes, int n_in,
                              void* d_out, int out_size)
{
    const float* x     = (const float*)d_in[0];
    const float* Wq    = (const float*)d_in[1];
    const float* Wk    = (const float*)d_in[2];
    const float* Wv    = (const float*)d_in[3];
    const float* Wproj = (const float*)d_in[4];
    const float* bproj = (const float*)d_in[5];
    const float* W1    = (const float*)d_in[6];
    const float* b1    = (const float*)d_in[7];
    const float* W2    = (const float*)d_in[8];
    const float* b2    = (const float*)d_in[9];
    const float* ln1w  = (const float*)d_in[10];
    const float* ln1b  = (const float*)d_in[11];
    const float* ln2w  = (const float*)d_in[12];
    const float* ln2b  = (const float*)d_in[13];
    float* out = (float*)d_out;

    __half *ph, *pqkv, *pattn, *pf1, *pwr;
    float *px2;
    cudaGetSymbolAddress((void**)&ph,    g_h);
    cudaGetSymbolAddress((void**)&pqkv,  g_qkv);
    cudaGetSymbolAddress((void**)&pattn, g_attn);
    cudaGetSymbolAddress((void**)&px2,   g_x2);
    cudaGetSymbolAddress((void**)&pf1,   g_f1);
    cudaGetSymbolAddress((void**)&pwr,   g_wr);

    const size_t M1 = (size_t)1024*1024;
    __half* Wqkvt = pwr;            // [3072][1024]
    __half* Wpt   = pwr + 3*M1;     // [1024][1024]
    __half* W1t   = pwr + 4*M1;     // [4096][1024]
    __half* W2t   = pwr + 8*M1;     // [1024][4096]

    constexpr int ST = 4;
    constexpr size_t SMEM_G = (size_t)2*ST*HG_STAGE;   // 81920 B

    auto* kh = hgemm<ST,1>;
    auto* kf = hgemm<ST,0>;
    cudaFuncSetAttribute(kh, cudaFuncAttributeMaxDynamicSharedMemorySize, (int)SMEM_G);
    cudaFuncSetAttribute(kf, cudaFuncAttributeMaxDynamicSharedMemorySize, (int)SMEM_G);
    cudaFuncSetAttribute(flash_kernel, cudaFuncAttributeMaxDynamicSharedMemorySize, (int)FA_SMEM);

    // 0) transpose + half-round all weights (batched: 4 square mats in one launch)
    {
        dim3 blk(32, 8);
        TP4 tp;
        tp.src[0] = Wq;    tp.dst[0] = Wqkvt;
        tp.src[1] = Wk;    tp.dst[1] = Wqkvt + M1;
        tp.src[2] = Wv;    tp.dst[2] = Wqkvt + 2*M1;
        tp.src[3] = Wproj; tp.dst[3] = Wpt;
        transpose_round_h4<<<dim3(32, 32, 4), blk>>>(tp);
        transpose_round_h<<<dim3(128, 32), blk>>>(W1, W1t, 1024, 4096);
        transpose_round_h<<<dim3(32, 128), blk>>>(W2, W2t, 4096, 1024);
    }

    // 1) LN1 -> half
    ln_kernel<<<BT, 256>>>(x, ln1w, ln1b, ph);

    // 2) fused QKV: h[BT,1024] @ Wqkv -> g_qkv (half out)
    kh<<<dim3(QKV_LD/128, BT/128), 256, SMEM_G>>>(ph, Wqkvt, nullptr, nullptr, pqkv,
        BT, QKV_LD, NEMBD, QKV_LD, 0);

    // 3) fused flash attention (all-f16 mma, heavy-first order) -> g_attn (half out)
    flash_kernel<<<dim3(SEQ/128, BATCH*NHEAD), 256, FA_SMEM>>>(pqkv, pattn);

    // 4) x2 = x + attn @ Wproj + bproj  (float out)
    kf<<<dim3(NEMBD/128, BT/128), 256, SMEM_G>>>(pattn, Wpt, bproj, x, px2,
        BT, NEMBD, NEMBD, NEMBD, 0);

    // 5) LN2 -> half
    ln_kernel<<<BT, 256>>>(px2, ln2w, ln2b, ph);

    // 6) f1 = relu(h2 @ W1 + b1) (half out)
    kh<<<dim3(FFDIM/128, BT/128), 256, SMEM_G>>>(ph, W1t, b1, nullptr, pf1,
        BT, FFDIM, NEMBD, FFDIM, 1);

    // 7) out = x2 + f1 @ W2 + b2 (float out)
    kf<<<dim3(NEMBD/128, BT/128), 256, SMEM_G>>>(pf1, W2t, b2, px2, out,
        BT, NEMBD, FFDIM, NEMBD, 0);
}